// round 1
// baseline (speedup 1.0000x reference)
#include <cuda_runtime.h>
#include <cstdint>

// Problem shape
#define NB  16
#define NL  2048
#define NH  768
#define ND  64
#define CK  128           // chunk length
#define NCH (NL/CK)       // 16 chunks
#define HT  128           // h-tile
#define NHT (NH/HT)       // 6 h-tiles
#define DH  (ND*NH)       // 49152

// Scratch (static device arrays — no allocation)
__device__ float g_E [NB*NL*ND];            // gathered embeddings            8.4 MB
__device__ float g_Fp[NB*NL*ND];            // (l+1) * (E @ w)                8.4 MB
__device__ float g_M [NB*NCH*ND*NH];        // chunk outer products -> excl. prefix  50 MB
__device__ float g_S [NB*NCH*CK*CK];        // masked intra-chunk scores      16.8 MB

// ---------------------------------------------------------------------------
// K0: embedding gather + Fp = (l+1) * E @ w
// 256 threads = 4 tokens x 64 dims
// ---------------------------------------------------------------------------
__global__ void k_embed(const void* __restrict__ xraw,
                        const float* __restrict__ ae,
                        const float* __restrict__ w)
{
    __shared__ float sW[ND][ND];   // 16 KB
    __shared__ float sE[4][ND];

    int tid = threadIdx.x;

    // Detect index dtype: int64 (odd 32-bit words all zero) vs int32.
    const int* xi = (const int*)xraw;
    int oddw = xi[((tid & 63) << 1) + 1];
    int is64 = __syncthreads_and(oddw == 0);

    for (int i = tid; i < ND * ND; i += 256)
        ((float*)sW)[i] = w[i];

    int q = tid >> 6;          // token within block
    int d = tid & 63;
    int t = blockIdx.x * 4 + q;     // global token index (b*L + l)
    int l = t & (NL - 1);

    long long v;
    if (is64) v = ((const long long*)xraw)[t];
    else      v = (long long)xi[t];

    float e = ae[v * ND + d];
    sE[q][d] = e;
    g_E[(size_t)t * ND + d] = e;
    __syncthreads();

    float acc = 0.f;
    #pragma unroll
    for (int k = 0; k < ND; k++)
        acc += sE[q][k] * sW[k][d];

    g_Fp[(size_t)t * ND + d] = (float)(l + 1) * acc;
}

// ---------------------------------------------------------------------------
// Shared-memory loaders
// ---------------------------------------------------------------------------

// Load a [128 rows x 32 cols] global slice (row stride gstride floats),
// TRANSPOSED into st[32][128]. 256 threads, coalesced 128B global reads.
__device__ __forceinline__ void loadT_128x32(const float* __restrict__ g, int gstride,
                                             float st[32][CK], int tid)
{
    int f4 = tid & 7;        // 0..7  -> col group (4 floats)
    int r0 = tid >> 3;       // 0..31
    #pragma unroll
    for (int rep = 0; rep < 4; rep++) {
        int row = r0 + rep * 32;
        float4 v = *(const float4*)(g + (size_t)row * gstride + f4 * 4);
        st[f4*4 + 0][row] = v.x;
        st[f4*4 + 1][row] = v.y;
        st[f4*4 + 2][row] = v.z;
        st[f4*4 + 3][row] = v.w;
    }
}

// Load a [32 rows x 128 cols] global slice into sb[32][128], natural layout.
__device__ __forceinline__ void loadB_32x128(const float* __restrict__ g, int gstride,
                                             float sb[32][HT], int tid)
{
    int f4  = tid & 31;      // 0..31 -> col group
    int row = tid >> 5;      // 0..7
    #pragma unroll
    for (int rep = 0; rep < 4; rep++) {
        float4 v = *(const float4*)(g + (size_t)(row + rep*8) * gstride + f4 * 4);
        *(float4*)&sb[row + rep*8][f4 * 4] = v;
    }
}

// 8x8 micro-tile GEMM over a 32-deep k-slab: acc[r][s] += A_t[k][tj*8+r]*B[k][tn*8+s]
#define MM32(SA, SB, TN) do {                                               \
    _Pragma("unroll 8")                                                     \
    for (int kk = 0; kk < 32; kk++) {                                       \
        float4 a0 = *(const float4*)&SA[kk][tj*8];                          \
        float4 a1 = *(const float4*)&SA[kk][tj*8 + 4];                      \
        float4 b0 = *(const float4*)&SB[kk][(TN)*8];                        \
        float4 b1 = *(const float4*)&SB[kk][(TN)*8 + 4];                    \
        float av[8] = {a0.x,a0.y,a0.z,a0.w,a1.x,a1.y,a1.z,a1.w};            \
        float bv[8] = {b0.x,b0.y,b0.z,b0.w,b1.x,b1.y,b1.z,b1.w};            \
        _Pragma("unroll")                                                   \
        for (int r = 0; r < 8; r++)                                         \
            _Pragma("unroll")                                               \
            for (int s = 0; s < 8; s++)                                     \
                acc[r][s] += av[r] * bv[s];                                 \
    }                                                                       \
} while (0)

// ---------------------------------------------------------------------------
// K1a: per-chunk outer products  G[b][c] = Fp_c^T @ X_c   ([64 x C]@[C x H])
// grid (NHT, NCH, NB), 256 threads, output tile 64 x 128, micro 4x8
// ---------------------------------------------------------------------------
__global__ void k_outer(const float* __restrict__ bx)
{
    __shared__ float sF[32][ND];   // [i][d]  8 KB
    __shared__ float sX[32][HT];   // [i][h] 16 KB

    int tid = threadIdx.x;
    int ht = blockIdx.x, c = blockIdx.y, b = blockIdx.z;
    int h0 = ht * HT;

    const float* fpb = g_Fp + ((size_t)b * NL + c * CK) * ND;
    const float* xb  = bx   + ((size_t)b * NL + c * CK) * NH + h0;

    int td = tid & 15;       // d-quad: d = td*4 .. td*4+3
    int th = tid >> 4;       // h-oct : h = h0 + th*8 ..

    float acc[4][8];
    #pragma unroll
    for (int r = 0; r < 4; r++)
        #pragma unroll
        for (int s = 0; s < 8; s++) acc[r][s] = 0.f;

    for (int it = 0; it < CK; it += 32) {
        {   // sF: 32x64 natural
            int f4 = tid & 15, row = tid >> 4;    // row 0..15
            #pragma unroll
            for (int rep = 0; rep < 2; rep++) {
                float4 v = *(const float4*)(fpb + (size_t)(it + row + rep*16) * ND + f4 * 4);
                *(float4*)&sF[row + rep*16][f4 * 4] = v;
            }
        }
        loadB_32x128(xb + (size_t)it * NH, NH, sX, tid);
        __syncthreads();

        #pragma unroll 8
        for (int i = 0; i < 32; i++) {
            float4 a0 = *(const float4*)&sF[i][td * 4];
            float4 b0 = *(const float4*)&sX[i][th * 8];
            float4 b1 = *(const float4*)&sX[i][th * 8 + 4];
            float av[4] = {a0.x, a0.y, a0.z, a0.w};
            float bv[8] = {b0.x,b0.y,b0.z,b0.w,b1.x,b1.y,b1.z,b1.w};
            #pragma unroll
            for (int r = 0; r < 4; r++)
                #pragma unroll
                for (int s = 0; s < 8; s++)
                    acc[r][s] += av[r] * bv[s];
        }
        __syncthreads();
    }

    float* gout = g_M + ((size_t)(b * NCH + c)) * DH + h0;
    #pragma unroll
    for (int r = 0; r < 4; r++) {
        float* row = gout + (size_t)(td * 4 + r) * NH + th * 8;
        *(float4*)row       = make_float4(acc[r][0], acc[r][1], acc[r][2], acc[r][3]);
        *(float4*)(row + 4) = make_float4(acc[r][4], acc[r][5], acc[r][6], acc[r][7]);
    }
}

// ---------------------------------------------------------------------------
// K1b: intra-chunk scores  S[b][c][j][i] = E_c[j] . Fp_c[i], zeroed for i >= j
// grid (NCH, NB), 256 threads, output 128x128, micro 8x8
// ---------------------------------------------------------------------------
__global__ void k_scores()
{
    __shared__ float sEt[32][CK];  // [d][j] 16 KB
    __shared__ float sFt[32][CK];  // [d][i] 16 KB

    int tid = threadIdx.x;
    int c = blockIdx.x, b = blockIdx.y;

    const float* Eb  = g_E  + ((size_t)b * NL + c * CK) * ND;
    const float* Fpb = g_Fp + ((size_t)b * NL + c * CK) * ND;

    int tj = tid & 15;      // j-oct
    int ti = tid >> 4;      // i-oct

    float acc[8][8];
    #pragma unroll
    for (int r = 0; r < 8; r++)
        #pragma unroll
        for (int s = 0; s < 8; s++) acc[r][s] = 0.f;

    for (int dt = 0; dt < ND; dt += 32) {
        loadT_128x32(Eb  + dt, ND, sEt, tid);
        loadT_128x32(Fpb + dt, ND, sFt, tid);
        __syncthreads();
        MM32(sEt, sFt, ti);
        __syncthreads();
    }

    float* Sout = g_S + ((size_t)(b * NCH + c)) * CK * CK;
    #pragma unroll
    for (int r = 0; r < 8; r++) {
        int j = tj * 8 + r;
        float* row = Sout + (size_t)j * CK + ti * 8;
        float v[8];
        #pragma unroll
        for (int s = 0; s < 8; s++)
            v[s] = (ti * 8 + s < j) ? acc[r][s] : 0.f;   // strict causal mask
        *(float4*)row       = make_float4(v[0], v[1], v[2], v[3]);
        *(float4*)(row + 4) = make_float4(v[4], v[5], v[6], v[7]);
    }
}

// ---------------------------------------------------------------------------
// K2: exclusive prefix over chunks, in place on g_M.  One thread per (b,d,h).
// ---------------------------------------------------------------------------
__global__ void k_prefix()
{
    int idx = blockIdx.x * 256 + threadIdx.x;     // < NB*DH
    int b  = idx / DH;
    int dh = idx - b * DH;
    float run = 0.f;
    size_t p = (size_t)b * NCH * DH + dh;
    #pragma unroll
    for (int c = 0; c < NCH; c++) {
        float v = g_M[p];
        g_M[p] = run;
        run += v;
        p += DH;
    }
}

// ---------------------------------------------------------------------------
// K3: out = X + diag(1/(j+1)) * ( E_c @ M_c  +  tril(S_c,-1) @ X_c )
// Single GEMM with K = 64 (E|M) + 128 (S|X) = 192, in 32-deep slabs.
// grid (NHT, NCH, NB), 256 threads, output tile 128x128, micro 8x8
// ---------------------------------------------------------------------------
__global__ void k_final(const float* __restrict__ bx, float* __restrict__ out)
{
    __shared__ float sAt[32][CK];  // transposed A slab 16 KB
    __shared__ float sB [32][HT];  // B slab            16 KB

    int tid = threadIdx.x;
    int ht = blockIdx.x, c = blockIdx.y, b = blockIdx.z;
    int h0 = ht * HT;

    int tj = tid & 15;      // j-oct
    int th = tid >> 4;      // h-oct

    const float* Eb = g_E + ((size_t)b * NL + c * CK) * ND;
    const float* Mb = g_M + ((size_t)(b * NCH + c)) * DH + h0;
    const float* Sb = g_S + ((size_t)(b * NCH + c)) * CK * CK;
    const float* Xb = bx  + ((size_t)b * NL + c * CK) * NH + h0;

    float acc[8][8];
    #pragma unroll
    for (int r = 0; r < 8; r++)
        #pragma unroll
        for (int s = 0; s < 8; s++) acc[r][s] = 0.f;

    // Inter-chunk part: E_c @ M_c  (K = 64, two slabs)
    for (int kt = 0; kt < 2; kt++) {
        loadT_128x32(Eb + kt * 32, ND, sAt, tid);
        loadB_32x128(Mb + (size_t)(kt * 32) * NH, NH, sB, tid);
        __syncthreads();
        MM32(sAt, sB, th);
        __syncthreads();
    }

    // Intra-chunk part: tril(S) @ X_c  (K = 128, four slabs; S pre-masked)
    for (int kt = 0; kt < 4; kt++) {
        loadT_128x32(Sb + kt * 32, CK, sAt, tid);
        loadB_32x128(Xb + (size_t)(kt * 32) * NH, NH, sB, tid);
        __syncthreads();
        MM32(sAt, sB, th);
        __syncthreads();
    }

    // Epilogue: out = x + (1/(j+1)) * acc
    float* ob = out + ((size_t)b * NL + c * CK) * NH + h0;
    #pragma unroll
    for (int r = 0; r < 8; r++) {
        int j = tj * 8 + r;
        float rj = 1.f / (float)(c * CK + j + 1);
        const float* xr = Xb + (size_t)j * NH + th * 8;
        float*       orow = ob + (size_t)j * NH + th * 8;
        float4 x0 = *(const float4*)xr;
        float4 x1 = *(const float4*)(xr + 4);
        *(float4*)orow       = make_float4(x0.x + rj * acc[r][0],
                                           x0.y + rj * acc[r][1],
                                           x0.z + rj * acc[r][2],
                                           x0.w + rj * acc[r][3]);
        *(float4*)(orow + 4) = make_float4(x1.x + rj * acc[r][4],
                                           x1.y + rj * acc[r][5],
                                           x1.z + rj * acc[r][6],
                                           x1.w + rj * acc[r][7]);
    }
}

// ---------------------------------------------------------------------------
extern "C" void kernel_launch(void* const* d_in, const int* in_sizes, int n_in,
                              void* d_out, int out_size)
{
    const float* bx = (const float*)d_in[0];   // bert_x [B,L,H] f32
    const void*  x  = d_in[1];                 // x      [B,L]   int32 or int64 (auto-detected)
    const float* ae = (const float*)d_in[2];   // ae     [V,D]   f32
    const float* w  = (const float*)d_in[3];   // w      [D,D]   f32
    float* out = (float*)d_out;                // [B,L,H] f32

    (void)in_sizes; (void)n_in; (void)out_size;

    k_embed <<<NB * NL / 4, 256>>>(x, ae, w);
    k_outer <<<dim3(NHT, NCH, NB), 256>>>(bx);
    k_scores<<<dim3(NCH, NB), 256>>>();
    k_prefix<<<NB * DH / 256, 256>>>();
    k_final <<<dim3(NHT, NCH, NB), 256>>>(bx, out);
}